// round 6
// baseline (speedup 1.0000x reference)
#include <cuda_runtime.h>
#include <cstdint>

// Problem constants (fixed by the reference setup)
#define NB 65536        // batch rows
#define NF 512          // in_features
#define NK 1299         // number of centers
#define THREADS 256
#define WARPS_PER_BLOCK (THREADS / 32)        // 8
#define NBLOCKS (NB / WARPS_PER_BLOCK)        // 8192 blocks, 1 warp per row

// Scratch for deterministic loss reduction (no device allocs allowed)
__device__ float        g_partials[NBLOCKS];
__device__ unsigned int g_ticket = 0;          // reset by last block each launch

__global__ __launch_bounds__(THREADS)
void fused_kernel(const float* __restrict__ input,
                  const float* __restrict__ factor,
                  const int* __restrict__ label,     // JAX downcasts int64->int32
                  const float* __restrict__ centers,
                  float* __restrict__ out)           // out[0]=loss, out[1..NB]=predict_a
{
    const int warp = threadIdx.x >> 5;
    const int lane = threadIdx.x & 31;
    const int b = blockIdx.x * WARPS_PER_BLOCK + warp;

    const float4* in4 = reinterpret_cast<const float4*>(input + (size_t)b * NF);
    int c = label[b];
    c = (c < 0) ? 0 : (c >= NK ? NK - 1 : c);          // in-bounds insurance
    const float4* ce4 = reinterpret_cast<const float4*>(centers + (size_t)c * NF);

    // 4 independent float4 loads per lane from input (coalesced, front-batched)
    // + 4 from centers (L2-resident after warm-up: whole table = 2.6 MB).
    float acc = 0.0f;
#pragma unroll
    for (int i = 0; i < 4; i++) {
        float4 a = in4[lane + 32 * i];
        float4 w = ce4[lane + 32 * i];
        acc += a.x * w.x + a.y * w.y + a.z * w.z + a.w * w.w;
    }

    // Warp reduction
#pragma unroll
    for (int o = 16; o; o >>= 1)
        acc += __shfl_xor_sync(0xffffffffu, acc, o);

    __shared__ float s_loss[WARPS_PER_BLOCK];
    if (lane == 0) {
        float p = 12.0f * tanhf(acc);
        out[1 + b] = p;
        float d = p - factor[b];
        float ad = fabsf(d);
        s_loss[warp] = (ad < 1.0f) ? 0.5f * d * d : (ad - 0.5f);
    }
    __syncthreads();

    // Warp 0 reduces the 8 per-warp terms, publishes the block partial.
    // NO __threadfence (gpu-scope fence = CCTL.IVALL = L1D flush, 8192x!).
    // Ordering via release/acquire atomic instead; L2 is the coherence point.
    __shared__ bool s_is_last;
    if (warp == 0) {
        float t = (lane < WARPS_PER_BLOCK) ? s_loss[lane] : 0.0f;
#pragma unroll
        for (int o = 4; o; o >>= 1)
            t += __shfl_xor_sync(0xffffffffu, t, o);
        if (lane == 0) {
            __stcg(&g_partials[blockIdx.x], t);        // write through to L2
            unsigned int ticket;
            asm volatile("atom.global.add.acq_rel.gpu.u32 %0, [%1], %2;"
                         : "=r"(ticket)
                         : "l"(&g_ticket), "r"(1u)
                         : "memory");
            s_is_last = (ticket == (unsigned int)(gridDim.x - 1));
        }
    }
    __syncthreads();

    // Last block: deterministic tree-reduce of all partials (fixed order).
    if (s_is_last) {
        __shared__ float s[THREADS];
        float t = 0.0f;
        for (int i = threadIdx.x; i < NBLOCKS; i += THREADS)
            t += __ldcg(&g_partials[i]);               // L2-direct (coherent)
        s[threadIdx.x] = t;
        __syncthreads();
#pragma unroll
        for (int o = THREADS / 2; o; o >>= 1) {
            if (threadIdx.x < o) s[threadIdx.x] += s[threadIdx.x + o];
            __syncthreads();
        }
        if (threadIdx.x == 0) {
            out[0] = s[0] * (1.0f / (float)NB);
            g_ticket = 0;                               // clean state for next replay
        }
    }
}

extern "C" void kernel_launch(void* const* d_in, const int* in_sizes, int n_in,
                              void* d_out, int out_size)
{
    // metadata order follows setup_inputs: input, factor, label, centers
    const float* input   = (const float*)d_in[0];
    const float* factor  = (const float*)d_in[1];
    const int*   label   = (const int*)d_in[2];
    const float* centers = (const float*)d_in[3];

    float* out = (float*)d_out;   // out[0]=loss, out[1..NB]=predict_a

    fused_kernel<<<NBLOCKS, THREADS>>>(input, factor, label, centers, out);
}

// round 7
// speedup vs baseline: 1.2487x; 1.2487x over previous
#include <cuda_runtime.h>
#include <cstdint>

// Problem constants (fixed by the reference setup)
#define NB 65536        // batch rows
#define NF 512          // in_features
#define NK 1299         // number of centers
#define WARPS_PER_BLOCK 8
#define NBLOCKS (NB / WARPS_PER_BLOCK)   // 8192 blocks, 1 warp per row

// Scratch for deterministic loss reduction (no device allocs allowed)
__device__ float g_partials[NBLOCKS];

// Kernel 1: per-row gathered dot product + tanh + smooth-L1 term.
// One warp per row: 512 floats = 128 float4 = 4 float4 per lane.
// (This exact configuration measured ~26us; keep untouched.)
__global__ __launch_bounds__(WARPS_PER_BLOCK * 32)
void predict_kernel(const float* __restrict__ input,
                    const float* __restrict__ factor,
                    const int* __restrict__ label,     // JAX downcasts int64->int32
                    const float* __restrict__ centers,
                    float* __restrict__ pred_out)      // points at d_out+1
{
    const int warp = threadIdx.x >> 5;
    const int lane = threadIdx.x & 31;
    const int b = blockIdx.x * WARPS_PER_BLOCK + warp;

    const float4* in4 = reinterpret_cast<const float4*>(input + (size_t)b * NF);
    int c = label[b];
    c = (c < 0) ? 0 : (c >= NK ? NK - 1 : c);          // in-bounds insurance
    const float4* ce4 = reinterpret_cast<const float4*>(centers + (size_t)c * NF);

    float acc = 0.0f;
#pragma unroll
    for (int i = 0; i < 4; i++) {
        float4 a = in4[lane + 32 * i];
        float4 w = ce4[lane + 32 * i];
        acc += a.x * w.x + a.y * w.y + a.z * w.z + a.w * w.w;
    }

#pragma unroll
    for (int o = 16; o; o >>= 1)
        acc += __shfl_xor_sync(0xffffffffu, acc, o);

    __shared__ float s_loss[WARPS_PER_BLOCK];
    if (lane == 0) {
        float p = 12.0f * tanhf(acc);
        pred_out[b] = p;
        float d = p - factor[b];
        float ad = fabsf(d);
        s_loss[warp] = (ad < 1.0f) ? 0.5f * d * d : (ad - 0.5f);
    }
    __syncthreads();

    if (threadIdx.x == 0) {
        float t = 0.0f;
#pragma unroll
        for (int i = 0; i < WARPS_PER_BLOCK; i++) t += s_loss[i];
        g_partials[blockIdx.x] = t;
    }
}

// Kernel 2: deterministic reduction of 8192 partials.
// 1024 threads, 8 independent front-batched loads per thread (MLP=8):
// one overlapped L2 round-trip instead of a serialized strided loop.
#define RTHREADS 1024
__global__ __launch_bounds__(RTHREADS)
void loss_reduce_kernel(float* __restrict__ out)
{
    const int tid  = threadIdx.x;
    const int warp = tid >> 5;
    const int lane = tid & 31;

    // Each thread owns 8 consecutive-stride slots: fixed order -> deterministic.
    float v0 = g_partials[tid + 0 * RTHREADS];
    float v1 = g_partials[tid + 1 * RTHREADS];
    float v2 = g_partials[tid + 2 * RTHREADS];
    float v3 = g_partials[tid + 3 * RTHREADS];
    float v4 = g_partials[tid + 4 * RTHREADS];
    float v5 = g_partials[tid + 5 * RTHREADS];
    float v6 = g_partials[tid + 6 * RTHREADS];
    float v7 = g_partials[tid + 7 * RTHREADS];
    float t = ((v0 + v1) + (v2 + v3)) + ((v4 + v5) + (v6 + v7));

#pragma unroll
    for (int o = 16; o; o >>= 1)
        t += __shfl_xor_sync(0xffffffffu, t, o);

    __shared__ float s[RTHREADS / 32];
    if (lane == 0) s[warp] = t;
    __syncthreads();

    if (warp == 0) {
        float u = s[lane];   // 32 warps -> 32 values
#pragma unroll
        for (int o = 16; o; o >>= 1)
            u += __shfl_xor_sync(0xffffffffu, u, o);
        if (lane == 0)
            out[0] = u * (1.0f / (float)NB);
    }
}

extern "C" void kernel_launch(void* const* d_in, const int* in_sizes, int n_in,
                              void* d_out, int out_size)
{
    // metadata order follows setup_inputs: input, factor, label, centers
    const float* input   = (const float*)d_in[0];
    const float* factor  = (const float*)d_in[1];
    const int*   label   = (const int*)d_in[2];
    const float* centers = (const float*)d_in[3];

    float* out = (float*)d_out;   // out[0]=loss, out[1..NB]=predict_a
    float* pred_out = out + 1;

    predict_kernel<<<NBLOCKS, WARPS_PER_BLOCK * 32>>>(input, factor, label, centers, pred_out);
    loss_reduce_kernel<<<1, RTHREADS>>>(out);
}

// round 8
// speedup vs baseline: 1.3213x; 1.0581x over previous
#include <cuda_runtime.h>
#include <cstdint>

// Problem constants (fixed by the reference setup)
#define NB 65536        // batch rows
#define NF 512          // in_features
#define NK 1299         // number of centers
#define WARPS_PER_BLOCK 8
#define NBLOCKS (NB / WARPS_PER_BLOCK)   // 8192 blocks, 1 warp per row

// Fixed-point loss accumulator: integer atomics are exactly commutative, so
// the result is bit-deterministic regardless of block scheduling order.
// Partials are >= 0 and <= ~128; scale 2^30 => max total ~2^50 < 2^63.
#define LOSS_SCALE 1073741824.0f   // 2^30
__device__ unsigned long long g_loss_acc;   // zero-initialized; finisher resets it

// Kernel 1: per-row gathered dot product + tanh + smooth-L1 term.
// One warp per row: 512 floats = 128 float4 = 4 float4 per lane.
__global__ __launch_bounds__(WARPS_PER_BLOCK * 32)
void predict_kernel(const float* __restrict__ input,
                    const float* __restrict__ factor,
                    const int* __restrict__ label,     // JAX downcasts int64->int32
                    const float* __restrict__ centers,
                    float* __restrict__ pred_out)      // points at d_out+1
{
    const int warp = threadIdx.x >> 5;
    const int lane = threadIdx.x & 31;
    const int b = blockIdx.x * WARPS_PER_BLOCK + warp;

    const float4* in4 = reinterpret_cast<const float4*>(input + (size_t)b * NF);
    int c = label[b];
    c = (c < 0) ? 0 : (c >= NK ? NK - 1 : c);          // in-bounds insurance
    const float4* ce4 = reinterpret_cast<const float4*>(centers + (size_t)c * NF);

    // input: zero reuse -> bypass L1 (__ldcg), keep L1 capacity for centers.
    float acc = 0.0f;
#pragma unroll
    for (int i = 0; i < 4; i++) {
        float4 a = __ldcg(&in4[lane + 32 * i]);
        float4 w = ce4[lane + 32 * i];
        acc += a.x * w.x + a.y * w.y + a.z * w.z + a.w * w.w;
    }

#pragma unroll
    for (int o = 16; o; o >>= 1)
        acc += __shfl_xor_sync(0xffffffffu, acc, o);

    __shared__ float s_loss[WARPS_PER_BLOCK];
    if (lane == 0) {
        float p = 12.0f * tanhf(acc);
        __stcg(&pred_out[b], p);                       // streamed output, skip L1
        float d = p - factor[b];
        float ad = fabsf(d);
        s_loss[warp] = (ad < 1.0f) ? 0.5f * d * d : (ad - 0.5f);
    }
    __syncthreads();

    if (threadIdx.x == 0) {
        float t = 0.0f;
#pragma unroll
        for (int i = 0; i < WARPS_PER_BLOCK; i++) t += s_loss[i];
        // Deterministic integer accumulation (one atomic per block).
        unsigned long long q = (unsigned long long)(t * LOSS_SCALE + 0.5f);
        atomicAdd(&g_loss_acc, q);
    }
}

// Kernel 2: trivial finisher — scale the fixed-point sum, reset accumulator.
__global__ void loss_finish_kernel(float* __restrict__ out)
{
    unsigned long long q = g_loss_acc;
    out[0] = (float)((double)q * (1.0 / ((double)LOSS_SCALE * (double)NB)));
    g_loss_acc = 0ull;                                 // clean state for next replay
}

extern "C" void kernel_launch(void* const* d_in, const int* in_sizes, int n_in,
                              void* d_out, int out_size)
{
    // metadata order follows setup_inputs: input, factor, label, centers
    const float* input   = (const float*)d_in[0];
    const float* factor  = (const float*)d_in[1];
    const int*   label   = (const int*)d_in[2];
    const float* centers = (const float*)d_in[3];

    float* out = (float*)d_out;   // out[0]=loss, out[1..NB]=predict_a
    float* pred_out = out + 1;

    predict_kernel<<<NBLOCKS, WARPS_PER_BLOCK * 32>>>(input, factor, label, centers, pred_out);
    loss_finish_kernel<<<1, 1>>>(out);
}